// round 11
// baseline (speedup 1.0000x reference)
#include <cuda_runtime.h>
#include <cstdint>

// Problem constants
constexpr int BATCH = 4;
constexpr int SEQ   = 2048;
constexpr int DIM   = 1024;           // D_IN == D_OUT
constexpr int MTOT  = BATCH * SEQ;    // 8192

// Scratch for Q, K, V projections (device globals: allocation-free rule)
__device__ float g_q[(size_t)MTOT * DIM];
__device__ float g_k[(size_t)MTOT * DIM];
__device__ float g_v[(size_t)MTOT * DIM];

#define NEG_INF_F (__int_as_float(0xff800000))

constexpr int BK  = 8;     // K-tile depth
constexpr int PAD = 4;     // smem row padding: row = 132 floats = 528B (16B mult.)

// ---------------------------------------------------------------------------
// Shared compute core: 8x8 per-thread tile in 4 quadrants over a 128x128
// block tile.  All smem reads are explicit float4 (16B-aligned by
// construction).
// ---------------------------------------------------------------------------
__device__ __forceinline__ void mma_tile(
    const float (*As)[128 + PAD], const float (*Bs)[128 + PAD],
    int tx, int ty, float acc[8][8])
{
    #pragma unroll
    for (int k = 0; k < BK; k++) {
        float4 a0 = *reinterpret_cast<const float4*>(&As[k][ty * 4]);
        float4 a1 = *reinterpret_cast<const float4*>(&As[k][64 + ty * 4]);
        float4 b0 = *reinterpret_cast<const float4*>(&Bs[k][tx * 4]);
        float4 b1 = *reinterpret_cast<const float4*>(&Bs[k][64 + tx * 4]);
        float ar[8] = {a0.x, a0.y, a0.z, a0.w, a1.x, a1.y, a1.z, a1.w};
        float br[8] = {b0.x, b0.y, b0.z, b0.w, b1.x, b1.y, b1.z, b1.w};
        #pragma unroll
        for (int u = 0; u < 8; u++)
            #pragma unroll
            for (int v = 0; v < 8; v++)
                acc[u][v] = fmaf(ar[u], br[v], acc[u][v]);
    }
}

// ---------------------------------------------------------------------------
// Kernel 1: QKV projection.  C = x @ W{q,k,v}; Q additionally scaled by 1/32
// (exact power-of-two fold of the softmax 1/sqrt(d) scale).
// Double-buffered smem, BK=8, 256 threads, grid = (8, 64, 3).
// launch_bounds(256, 2): cap regs at 128 to guarantee 2 blocks/SM.
// ---------------------------------------------------------------------------
__global__ __launch_bounds__(256, 2) void qkv_gemm(
    const float* __restrict__ x,
    const float* __restrict__ Wq,
    const float* __restrict__ Wk,
    const float* __restrict__ Wv)
{
    __shared__ float As[2][BK][128 + PAD];
    __shared__ float Bs[2][BK][128 + PAD];

    const int tid = threadIdx.x;
    const int tx  = tid & 15;
    const int ty  = tid >> 4;
    const int rowBase = blockIdx.y * 128;
    const int colBase = blockIdx.x * 128;

    const float* W;
    float* C;
    float alpha;
    switch (blockIdx.z) {
        case 0:  W = Wq; C = g_q; alpha = 0.03125f; break;
        case 1:  W = Wk; C = g_k; alpha = 1.0f;     break;
        default: W = Wv; C = g_v; alpha = 1.0f;     break;
    }

    // A loader: 128 rows x 8 cols -> one float4 per thread; advance +BK/iter
    const int ar_ = tid >> 1;            // 0..127
    const int ac_ = (tid & 1) * 4;       // 0 or 4
    const float* aPtr = &x[(size_t)(rowBase + ar_) * DIM + ac_];
    // B loader: 8 rows x 128 cols; advance +BK*DIM/iter
    const int br_ = tid >> 5;            // 0..7
    const int bc_ = (tid & 31) * 4;      // 0..124
    const float* bPtr = &W[(size_t)br_ * DIM + colBase + bc_];

    float acc[8][8];
    #pragma unroll
    for (int u = 0; u < 8; u++)
        #pragma unroll
        for (int v = 0; v < 8; v++) acc[u][v] = 0.0f;

    const int nt = DIM / BK;

    float4 apf = *reinterpret_cast<const float4*>(aPtr);
    float4 bpf = *reinterpret_cast<const float4*>(bPtr);
    As[0][ac_ + 0][ar_] = apf.x; As[0][ac_ + 1][ar_] = apf.y;
    As[0][ac_ + 2][ar_] = apf.z; As[0][ac_ + 3][ar_] = apf.w;
    *reinterpret_cast<float4*>(&Bs[0][br_][bc_]) = bpf;
    __syncthreads();

    for (int t = 0; t < nt; t++) {
        const int buf = t & 1;
        const bool more = (t + 1 < nt);
        if (more) {
            aPtr += BK;
            bPtr += (size_t)BK * DIM;
            apf = *reinterpret_cast<const float4*>(aPtr);
            bpf = *reinterpret_cast<const float4*>(bPtr);
        }
        mma_tile(As[buf], Bs[buf], tx, ty, acc);
        if (more) {
            As[1 - buf][ac_ + 0][ar_] = apf.x; As[1 - buf][ac_ + 1][ar_] = apf.y;
            As[1 - buf][ac_ + 2][ar_] = apf.z; As[1 - buf][ac_ + 3][ar_] = apf.w;
            *reinterpret_cast<float4*>(&Bs[1 - buf][br_][bc_]) = bpf;
            __syncthreads();
        }
    }

    #pragma unroll
    for (int u = 0; u < 8; u++) {
        int ru = rowBase + ((u < 4) ? (ty * 4 + u) : (64 + ty * 4 + (u - 4)));
        #pragma unroll
        for (int half = 0; half < 2; half++) {
            float4 vv;
            vv.x = acc[u][half * 4 + 0] * alpha;
            vv.y = acc[u][half * 4 + 1] * alpha;
            vv.z = acc[u][half * 4 + 2] * alpha;
            vv.w = acc[u][half * 4 + 3] * alpha;
            int cc = colBase + half * 64 + tx * 4;
            *reinterpret_cast<float4*>(&C[(size_t)ru * DIM + cc]) = vv;
        }
    }
}

// ---------------------------------------------------------------------------
// Kernel 2: scores = Q @ K^T (Q already carries 1/sqrt(d)).
// Strictly-lower tiles: full GEMM, plain stores.
// Diagonal tiles: GEMM + -inf mask for col > row.
// Strictly-upper tiles: zero-fill (their final softmax weights are exactly 0).
// grid = (16, 16, BATCH).
// ---------------------------------------------------------------------------
__global__ __launch_bounds__(256, 2) void scores_gemm(float* __restrict__ w)
{
    const int tid = threadIdx.x;
    const int rowBase = blockIdx.y * 128;
    const int colBase = blockIdx.x * 128;
    const int b = blockIdx.z;
    float* Wb = w + (size_t)b * SEQ * SEQ;

    if (blockIdx.x > blockIdx.y) {
        // Strictly-upper tile: final attention weights are exactly zero.
        const int r0 = tid >> 3;            // 0..31
        const int c4 = (tid & 7) * 4;       // 0..28
        float4 z = make_float4(0.f, 0.f, 0.f, 0.f);
        #pragma unroll
        for (int rr = 0; rr < 4; rr++) {
            int gr = rowBase + rr * 32 + r0;
            #pragma unroll
            for (int cc = 0; cc < 4; cc++) {
                *reinterpret_cast<float4*>(
                    &Wb[(size_t)gr * SEQ + colBase + cc * 32 + c4]) = z;
            }
        }
        return;
    }

    __shared__ float As[2][BK][128 + PAD];
    __shared__ float Bs[2][BK][128 + PAD];

    const int tx  = tid & 15;
    const int ty  = tid >> 4;

    const float* Q  = g_q + (size_t)b * SEQ * DIM;
    const float* Km = g_k + (size_t)b * SEQ * DIM;

    // Both operands K-major (NT gemm): same transposed-load geometry; +BK/iter
    const int ar_ = tid >> 1;
    const int ac_ = (tid & 1) * 4;
    const float* aPtr = &Q [(size_t)(rowBase + ar_) * DIM + ac_];
    const float* bPtr = &Km[(size_t)(colBase + ar_) * DIM + ac_];

    float acc[8][8];
    #pragma unroll
    for (int u = 0; u < 8; u++)
        #pragma unroll
        for (int v = 0; v < 8; v++) acc[u][v] = 0.0f;

    const int nt = DIM / BK;

    float4 apf = *reinterpret_cast<const float4*>(aPtr);
    float4 bpf = *reinterpret_cast<const float4*>(bPtr);
    As[0][ac_ + 0][ar_] = apf.x; As[0][ac_ + 1][ar_] = apf.y;
    As[0][ac_ + 2][ar_] = apf.z; As[0][ac_ + 3][ar_] = apf.w;
    Bs[0][ac_ + 0][ar_] = bpf.x; Bs[0][ac_ + 1][ar_] = bpf.y;
    Bs[0][ac_ + 2][ar_] = bpf.z; Bs[0][ac_ + 3][ar_] = bpf.w;
    __syncthreads();

    for (int t = 0; t < nt; t++) {
        const int buf = t & 1;
        const bool more = (t + 1 < nt);
        if (more) {
            aPtr += BK;
            bPtr += BK;
            apf = *reinterpret_cast<const float4*>(aPtr);
            bpf = *reinterpret_cast<const float4*>(bPtr);
        }
        mma_tile(As[buf], Bs[buf], tx, ty, acc);
        if (more) {
            As[1 - buf][ac_ + 0][ar_] = apf.x; As[1 - buf][ac_ + 1][ar_] = apf.y;
            As[1 - buf][ac_ + 2][ar_] = apf.z; As[1 - buf][ac_ + 3][ar_] = apf.w;
            Bs[1 - buf][ac_ + 0][ar_] = bpf.x; Bs[1 - buf][ac_ + 1][ar_] = bpf.y;
            Bs[1 - buf][ac_ + 2][ar_] = bpf.z; Bs[1 - buf][ac_ + 3][ar_] = bpf.w;
            __syncthreads();
        }
    }

    const bool diag = (blockIdx.x == blockIdx.y);
    #pragma unroll
    for (int u = 0; u < 8; u++) {
        int gr = rowBase + ((u < 4) ? (ty * 4 + u) : (64 + ty * 4 + (u - 4)));
        #pragma unroll
        for (int half = 0; half < 2; half++) {
            int c0 = colBase + half * 64 + tx * 4;
            float4 vv;
            if (diag) {
                vv.x = (c0 + 0 > gr) ? NEG_INF_F : acc[u][half * 4 + 0];
                vv.y = (c0 + 1 > gr) ? NEG_INF_F : acc[u][half * 4 + 1];
                vv.z = (c0 + 2 > gr) ? NEG_INF_F : acc[u][half * 4 + 2];
                vv.w = (c0 + 3 > gr) ? NEG_INF_F : acc[u][half * 4 + 3];
            } else {
                vv.x = acc[u][half * 4 + 0];
                vv.y = acc[u][half * 4 + 1];
                vv.z = acc[u][half * 4 + 2];
                vv.w = acc[u][half * 4 + 3];
            }
            *reinterpret_cast<float4*>(&Wb[(size_t)gr * SEQ + c0]) = vv;
        }
    }
}

// ---------------------------------------------------------------------------
// Kernel 3: causal row softmax, in place.  One 256-thread block per row.
// Row i reads/writes j in [0, i]; remainder of the diagonal 128-tile zeroed
// here (scalar to 16B boundary, then float4); strictly-upper tiles already
// zeroed by scores_gemm.
// ---------------------------------------------------------------------------
__device__ __forceinline__ float warpRedMax(float v) {
    #pragma unroll
    for (int o = 16; o > 0; o >>= 1) v = fmaxf(v, __shfl_xor_sync(0xffffffffu, v, o));
    return v;
}
__device__ __forceinline__ float warpRedSum(float v) {
    #pragma unroll
    for (int o = 16; o > 0; o >>= 1) v += __shfl_xor_sync(0xffffffffu, v, o);
    return v;
}

__global__ __launch_bounds__(256) void softmax_rows(float* __restrict__ w)
{
    const int row = blockIdx.x;        // 0..BATCH*SEQ-1
    const int b = row >> 11;           // / SEQ
    const int i = row & (SEQ - 1);
    float* p = w + (size_t)b * SEQ * SEQ + (size_t)i * SEQ;
    const int valid = i + 1;
    const int tid = threadIdx.x;
    const int lane = tid & 31;
    const int wid  = tid >> 5;

    __shared__ float red[8];
    __shared__ float bcast;

    float vals[8];
    int cnt = 0;
    float m = NEG_INF_F;
    #pragma unroll 4
    for (int j = tid; j < valid; j += 256) {
        vals[cnt] = p[j];
        m = fmaxf(m, vals[cnt]);
        cnt++;
    }
    m = warpRedMax(m);
    if (lane == 0) red[wid] = m;
    __syncthreads();
    if (tid == 0) {
        float mm = red[0];
        #pragma unroll
        for (int k = 1; k < 8; k++) mm = fmaxf(mm, red[k]);
        bcast = mm;
    }
    __syncthreads();
    m = bcast;

    float s = 0.0f;
    for (int c = 0; c < cnt; c++) {
        vals[c] = __expf(vals[c] - m);
        s += vals[c];
    }
    s = warpRedSum(s);
    __syncthreads();                   // red[] reuse
    if (lane == 0) red[wid] = s;
    __syncthreads();
    if (tid == 0) {
        float ss = 0.0f;
        #pragma unroll
        for (int k = 0; k < 8; k++) ss += red[k];
        bcast = 1.0f / ss;
    }
    __syncthreads();
    const float inv = bcast;

    cnt = 0;
    #pragma unroll 4
    for (int j = tid; j < valid; j += 256) p[j] = vals[cnt++] * inv;

    const int tileEnd  = (valid + 127) & ~127;         // multiple of 128
    const int vecStart = (valid + 3) & ~3;             // first 4-aligned index
    for (int j = valid + tid; j < vecStart && j < tileEnd; j += 256) p[j] = 0.0f;
    float4 z4 = make_float4(0.f, 0.f, 0.f, 0.f);
    for (int j4 = (vecStart >> 2) + tid; j4 < (tileEnd >> 2); j4 += 256)
        reinterpret_cast<float4*>(p)[j4] = z4;
}

// ---------------------------------------------------------------------------
// Kernel 4: att_output = att_weights @ V.  Causal truncation of the k-loop
// at the diagonal tile.  grid = (8, 16, BATCH).
// ---------------------------------------------------------------------------
__global__ __launch_bounds__(256, 2) void out_gemm(
    const float* __restrict__ w, float* __restrict__ out)
{
    __shared__ float As[2][BK][128 + PAD];
    __shared__ float Bs[2][BK][128 + PAD];

    const int tid = threadIdx.x;
    const int tx  = tid & 15;
    const int ty  = tid >> 4;
    const int qt  = blockIdx.y;
    const int rowBase = qt * 128;
    const int colBase = blockIdx.x * 128;
    const int b = blockIdx.z;

    const float* A  = w   + (size_t)b * SEQ * SEQ;   // [SEQ, SEQ]
    const float* Bv = g_v + (size_t)b * SEQ * DIM;   // [SEQ, DIM]
    float*       C  = out + (size_t)b * SEQ * DIM;

    const int ar_ = tid >> 1;
    const int ac_ = (tid & 1) * 4;
    const float* aPtr = &A[(size_t)(rowBase + ar_) * SEQ + ac_];
    const int br_ = tid >> 5;
    const int bc_ = (tid & 31) * 4;
    const float* bPtr = &Bv[(size_t)br_ * DIM + colBase + bc_];

    float acc[8][8];
    #pragma unroll
    for (int u = 0; u < 8; u++)
        #pragma unroll
        for (int v = 0; v < 8; v++) acc[u][v] = 0.0f;

    const int nt = ((qt + 1) * 128) / BK;   // causal truncation

    float4 apf = *reinterpret_cast<const float4*>(aPtr);
    float4 bpf = *reinterpret_cast<const float4*>(bPtr);
    As[0][ac_ + 0][ar_] = apf.x; As[0][ac_ + 1][ar_] = apf.y;
    As[0][ac_ + 2][ar_] = apf.z; As[0][ac_ + 3][ar_] = apf.w;
    *reinterpret_cast<float4*>(&Bs[0][br_][bc_]) = bpf;
    __syncthreads();

    for (int t = 0; t < nt; t++) {
        const int buf = t & 1;
        const bool more = (t + 1 < nt);
        if (more) {
            aPtr += BK;
            bPtr += (size_t)BK * DIM;
            apf = *reinterpret_cast<const float4*>(aPtr);
            bpf = *reinterpret_cast<const float4*>(bPtr);
        }
        mma_tile(As[buf], Bs[buf], tx, ty, acc);
        if (more) {
            As[1 - buf][ac_ + 0][ar_] = apf.x; As[1 - buf][ac_ + 1][ar_] = apf.y;
            As[1 - buf][ac_ + 2][ar_] = apf.z; As[1 - buf][ac_ + 3][ar_] = apf.w;
            *reinterpret_cast<float4*>(&Bs[1 - buf][br_][bc_]) = bpf;
            __syncthreads();
        }
    }

    #pragma unroll
    for (int u = 0; u < 8; u++) {
        int ru = rowBase + ((u < 4) ? (ty * 4 + u) : (64 + ty * 4 + (u - 4)));
        #pragma unroll
        for (int half = 0; half < 2; half++) {
            float4 vv;
            vv.x = acc[u][half * 4 + 0];
            vv.y = acc[u][half * 4 + 1];
            vv.z = acc[u][half * 4 + 2];
            vv.w = acc[u][half * 4 + 3];
            int cc = colBase + half * 64 + tx * 4;
            *reinterpret_cast<float4*>(&C[(size_t)ru * DIM + cc]) = vv;
        }
    }
}

// ---------------------------------------------------------------------------
// kernel_launch: x, Wq, Wk, Wv -> (att_output, att_weights) concatenated.
// ---------------------------------------------------------------------------
extern "C" void kernel_launch(void* const* d_in, const int* in_sizes, int n_in,
                              void* d_out, int out_size)
{
    const float* x  = (const float*)d_in[0];
    const float* Wq = (const float*)d_in[1];
    const float* Wk = (const float*)d_in[2];
    const float* Wv = (const float*)d_in[3];

    float* att_out = (float*)d_out;                               // B*S*D
    float* att_w   = (float*)d_out + (size_t)BATCH * SEQ * DIM;   // B*S*S

    qkv_gemm<<<dim3(DIM / 128, MTOT / 128, 3), 256>>>(x, Wq, Wk, Wv);
    scores_gemm<<<dim3(SEQ / 128, SEQ / 128, BATCH), 256>>>(att_w);
    softmax_rows<<<dim3(BATCH * SEQ), 256>>>(att_w);
    out_gemm<<<dim3(DIM / 128, SEQ / 128, BATCH), 256>>>(att_w, att_out);
}

// round 14
// speedup vs baseline: 1.1393x; 1.1393x over previous
#include <cuda_runtime.h>
#include <cstdint>

// Problem constants
constexpr int BATCH = 4;
constexpr int SEQ   = 2048;
constexpr int DIM   = 1024;           // D_IN == D_OUT
constexpr int MTOT  = BATCH * SEQ;    // 8192

// Scratch for Q, K, V projections (device globals: allocation-free rule)
__device__ float g_q[(size_t)MTOT * DIM];
__device__ float g_k[(size_t)MTOT * DIM];
__device__ float g_v[(size_t)MTOT * DIM];

#define NEG_INF_F (__int_as_float(0xff800000))

constexpr int BK  = 8;     // K-tile depth
constexpr int PAD = 4;     // smem row padding: row = 132 floats = 528B (16B mult.)

// ---------------------------------------------------------------------------
// Packed f32x2 helpers (sm_103a FFMA2 path).  Per-lane IEEE fp32 FMA —
// numerically identical to scalar fmaf.
// ---------------------------------------------------------------------------
__device__ __forceinline__ unsigned long long pack2(float lo, float hi) {
    unsigned long long r;
    asm("mov.b64 %0, {%1, %2};"
        : "=l"(r) : "r"(__float_as_uint(lo)), "r"(__float_as_uint(hi)));
    return r;
}
__device__ __forceinline__ void unpack2(unsigned long long v, float& lo, float& hi) {
    unsigned int a, b;
    asm("mov.b64 {%0, %1}, %2;" : "=r"(a), "=r"(b) : "l"(v));
    lo = __uint_as_float(a);
    hi = __uint_as_float(b);
}
__device__ __forceinline__ void fma2(unsigned long long& d,
                                     unsigned long long a,
                                     unsigned long long b) {
    asm("fma.rn.f32x2 %0, %1, %2, %3;" : "=l"(d) : "l"(a), "l"(b), "l"(d));
}

// ---------------------------------------------------------------------------
// Shared compute core: 8x8 per-thread tile (as 8x4 packed f32x2 pairs) in 4
// quadrants over a 128x128 block tile.  B pairs load directly as ulonglong2
// from 16B-aligned smem; A scalars are duplicated into both lanes.
// acc2[u][v] holds columns (2v, 2v+1) of the old acc[u][0..7] layout.
// ---------------------------------------------------------------------------
__device__ __forceinline__ void mma_tile(
    const float (*As)[128 + PAD], const float (*Bs)[128 + PAD],
    int tx, int ty, unsigned long long acc2[8][4])
{
    #pragma unroll
    for (int k = 0; k < BK; k++) {
        float4 a0 = *reinterpret_cast<const float4*>(&As[k][ty * 4]);
        float4 a1 = *reinterpret_cast<const float4*>(&As[k][64 + ty * 4]);
        ulonglong2 bp0 = *reinterpret_cast<const ulonglong2*>(&Bs[k][tx * 4]);
        ulonglong2 bp1 = *reinterpret_cast<const ulonglong2*>(&Bs[k][64 + tx * 4]);
        unsigned long long b2[4] = {bp0.x, bp0.y, bp1.x, bp1.y};
        float ar[8] = {a0.x, a0.y, a0.z, a0.w, a1.x, a1.y, a1.z, a1.w};
        #pragma unroll
        for (int u = 0; u < 8; u++) {
            unsigned long long a2 = pack2(ar[u], ar[u]);
            #pragma unroll
            for (int v = 0; v < 4; v++)
                fma2(acc2[u][v], a2, b2[v]);
        }
    }
}

// Unpack one row of packed accumulators into 8 floats (old acc[u][*] order).
__device__ __forceinline__ void unpack_row(const unsigned long long acc2u[4],
                                           float c[8]) {
    unpack2(acc2u[0], c[0], c[1]);
    unpack2(acc2u[1], c[2], c[3]);
    unpack2(acc2u[2], c[4], c[5]);
    unpack2(acc2u[3], c[6], c[7]);
}

// ---------------------------------------------------------------------------
// Kernel 1: QKV projection.  C = x @ W{q,k,v}; Q additionally scaled by 1/32
// (exact power-of-two fold of the softmax 1/sqrt(d) scale).
// Double-buffered smem, BK=8, 256 threads, grid = (8, 64, 3).
// ---------------------------------------------------------------------------
__global__ __launch_bounds__(256, 2) void qkv_gemm(
    const float* __restrict__ x,
    const float* __restrict__ Wq,
    const float* __restrict__ Wk,
    const float* __restrict__ Wv)
{
    __shared__ float As[2][BK][128 + PAD];
    __shared__ float Bs[2][BK][128 + PAD];

    const int tid = threadIdx.x;
    const int tx  = tid & 15;
    const int ty  = tid >> 4;
    const int rowBase = blockIdx.y * 128;
    const int colBase = blockIdx.x * 128;

    const float* W;
    float* C;
    float alpha;
    switch (blockIdx.z) {
        case 0:  W = Wq; C = g_q; alpha = 0.03125f; break;
        case 1:  W = Wk; C = g_k; alpha = 1.0f;     break;
        default: W = Wv; C = g_v; alpha = 1.0f;     break;
    }

    // A loader: 128 rows x 8 cols -> one float4 per thread; advance +BK/iter
    const int ar_ = tid >> 1;            // 0..127
    const int ac_ = (tid & 1) * 4;       // 0 or 4
    const float* aPtr = &x[(size_t)(rowBase + ar_) * DIM + ac_];
    // B loader: 8 rows x 128 cols; advance +BK*DIM/iter
    const int br_ = tid >> 5;            // 0..7
    const int bc_ = (tid & 31) * 4;      // 0..124
    const float* bPtr = &W[(size_t)br_ * DIM + colBase + bc_];

    unsigned long long acc2[8][4];
    #pragma unroll
    for (int u = 0; u < 8; u++)
        #pragma unroll
        for (int v = 0; v < 4; v++) acc2[u][v] = 0ULL;

    const int nt = DIM / BK;

    float4 apf = *reinterpret_cast<const float4*>(aPtr);
    float4 bpf = *reinterpret_cast<const float4*>(bPtr);
    As[0][ac_ + 0][ar_] = apf.x; As[0][ac_ + 1][ar_] = apf.y;
    As[0][ac_ + 2][ar_] = apf.z; As[0][ac_ + 3][ar_] = apf.w;
    *reinterpret_cast<float4*>(&Bs[0][br_][bc_]) = bpf;
    __syncthreads();

    for (int t = 0; t < nt; t++) {
        const int buf = t & 1;
        const bool more = (t + 1 < nt);
        if (more) {
            aPtr += BK;
            bPtr += (size_t)BK * DIM;
            apf = *reinterpret_cast<const float4*>(aPtr);
            bpf = *reinterpret_cast<const float4*>(bPtr);
        }
        mma_tile(As[buf], Bs[buf], tx, ty, acc2);
        if (more) {
            As[1 - buf][ac_ + 0][ar_] = apf.x; As[1 - buf][ac_ + 1][ar_] = apf.y;
            As[1 - buf][ac_ + 2][ar_] = apf.z; As[1 - buf][ac_ + 3][ar_] = apf.w;
            *reinterpret_cast<float4*>(&Bs[1 - buf][br_][bc_]) = bpf;
            __syncthreads();
        }
    }

    #pragma unroll
    for (int u = 0; u < 8; u++) {
        int ru = rowBase + ((u < 4) ? (ty * 4 + u) : (64 + ty * 4 + (u - 4)));
        float c[8];
        unpack_row(acc2[u], c);
        #pragma unroll
        for (int half = 0; half < 2; half++) {
            float4 vv;
            vv.x = c[half * 4 + 0] * alpha;
            vv.y = c[half * 4 + 1] * alpha;
            vv.z = c[half * 4 + 2] * alpha;
            vv.w = c[half * 4 + 3] * alpha;
            int cc = colBase + half * 64 + tx * 4;
            *reinterpret_cast<float4*>(&C[(size_t)ru * DIM + cc]) = vv;
        }
    }
}

// ---------------------------------------------------------------------------
// Kernel 2: scores = Q @ K^T (Q already carries 1/sqrt(d)).
// Strictly-lower tiles: full GEMM, plain stores.
// Diagonal tiles: GEMM + -inf mask for col > row.
// Strictly-upper tiles: zero-fill (their final softmax weights are exactly 0).
// grid = (16, 16, BATCH).
// ---------------------------------------------------------------------------
__global__ __launch_bounds__(256, 2) void scores_gemm(float* __restrict__ w)
{
    const int tid = threadIdx.x;
    const int rowBase = blockIdx.y * 128;
    const int colBase = blockIdx.x * 128;
    const int b = blockIdx.z;
    float* Wb = w + (size_t)b * SEQ * SEQ;

    if (blockIdx.x > blockIdx.y) {
        // Strictly-upper tile: final attention weights are exactly zero.
        const int r0 = tid >> 3;            // 0..31
        const int c4 = (tid & 7) * 4;       // 0..28
        float4 z = make_float4(0.f, 0.f, 0.f, 0.f);
        #pragma unroll
        for (int rr = 0; rr < 4; rr++) {
            int gr = rowBase + rr * 32 + r0;
            #pragma unroll
            for (int cc = 0; cc < 4; cc++) {
                *reinterpret_cast<float4*>(
                    &Wb[(size_t)gr * SEQ + colBase + cc * 32 + c4]) = z;
            }
        }
        return;
    }

    __shared__ float As[2][BK][128 + PAD];
    __shared__ float Bs[2][BK][128 + PAD];

    const int tx  = tid & 15;
    const int ty  = tid >> 4;

    const float* Q  = g_q + (size_t)b * SEQ * DIM;
    const float* Km = g_k + (size_t)b * SEQ * DIM;

    // Both operands K-major (NT gemm): same transposed-load geometry; +BK/iter
    const int ar_ = tid >> 1;
    const int ac_ = (tid & 1) * 4;
    const float* aPtr = &Q [(size_t)(rowBase + ar_) * DIM + ac_];
    const float* bPtr = &Km[(size_t)(colBase + ar_) * DIM + ac_];

    unsigned long long acc2[8][4];
    #pragma unroll
    for (int u = 0; u < 8; u++)
        #pragma unroll
        for (int v = 0; v < 4; v++) acc2[u][v] = 0ULL;

    const int nt = DIM / BK;

    float4 apf = *reinterpret_cast<const float4*>(aPtr);
    float4 bpf = *reinterpret_cast<const float4*>(bPtr);
    As[0][ac_ + 0][ar_] = apf.x; As[0][ac_ + 1][ar_] = apf.y;
    As[0][ac_ + 2][ar_] = apf.z; As[0][ac_ + 3][ar_] = apf.w;
    Bs[0][ac_ + 0][ar_] = bpf.x; Bs[0][ac_ + 1][ar_] = bpf.y;
    Bs[0][ac_ + 2][ar_] = bpf.z; Bs[0][ac_ + 3][ar_] = bpf.w;
    __syncthreads();

    for (int t = 0; t < nt; t++) {
        const int buf = t & 1;
        const bool more = (t + 1 < nt);
        if (more) {
            aPtr += BK;
            bPtr += BK;
            apf = *reinterpret_cast<const float4*>(aPtr);
            bpf = *reinterpret_cast<const float4*>(bPtr);
        }
        mma_tile(As[buf], Bs[buf], tx, ty, acc2);
        if (more) {
            As[1 - buf][ac_ + 0][ar_] = apf.x; As[1 - buf][ac_ + 1][ar_] = apf.y;
            As[1 - buf][ac_ + 2][ar_] = apf.z; As[1 - buf][ac_ + 3][ar_] = apf.w;
            Bs[1 - buf][ac_ + 0][ar_] = bpf.x; Bs[1 - buf][ac_ + 1][ar_] = bpf.y;
            Bs[1 - buf][ac_ + 2][ar_] = bpf.z; Bs[1 - buf][ac_ + 3][ar_] = bpf.w;
            __syncthreads();
        }
    }

    const bool diag = (blockIdx.x == blockIdx.y);
    #pragma unroll
    for (int u = 0; u < 8; u++) {
        int gr = rowBase + ((u < 4) ? (ty * 4 + u) : (64 + ty * 4 + (u - 4)));
        float c[8];
        unpack_row(acc2[u], c);
        #pragma unroll
        for (int half = 0; half < 2; half++) {
            int c0 = colBase + half * 64 + tx * 4;
            float4 vv;
            if (diag) {
                vv.x = (c0 + 0 > gr) ? NEG_INF_F : c[half * 4 + 0];
                vv.y = (c0 + 1 > gr) ? NEG_INF_F : c[half * 4 + 1];
                vv.z = (c0 + 2 > gr) ? NEG_INF_F : c[half * 4 + 2];
                vv.w = (c0 + 3 > gr) ? NEG_INF_F : c[half * 4 + 3];
            } else {
                vv.x = c[half * 4 + 0];
                vv.y = c[half * 4 + 1];
                vv.z = c[half * 4 + 2];
                vv.w = c[half * 4 + 3];
            }
            *reinterpret_cast<float4*>(&Wb[(size_t)gr * SEQ + c0]) = vv;
        }
    }
}

// ---------------------------------------------------------------------------
// Kernel 3: causal row softmax, in place.  One 256-thread block per row.
// Row i reads/writes j in [0, i]; remainder of the diagonal 128-tile zeroed
// here (scalar to 16B boundary, then float4); strictly-upper tiles already
// zeroed by scores_gemm.
// ---------------------------------------------------------------------------
__device__ __forceinline__ float warpRedMax(float v) {
    #pragma unroll
    for (int o = 16; o > 0; o >>= 1) v = fmaxf(v, __shfl_xor_sync(0xffffffffu, v, o));
    return v;
}
__device__ __forceinline__ float warpRedSum(float v) {
    #pragma unroll
    for (int o = 16; o > 0; o >>= 1) v += __shfl_xor_sync(0xffffffffu, v, o);
    return v;
}

__global__ __launch_bounds__(256) void softmax_rows(float* __restrict__ w)
{
    const int row = blockIdx.x;        // 0..BATCH*SEQ-1
    const int b = row >> 11;           // / SEQ
    const int i = row & (SEQ - 1);
    float* p = w + (size_t)b * SEQ * SEQ + (size_t)i * SEQ;
    const int valid = i + 1;
    const int tid = threadIdx.x;
    const int lane = tid & 31;
    const int wid  = tid >> 5;

    __shared__ float red[8];
    __shared__ float bcast;

    float vals[8];
    int cnt = 0;
    float m = NEG_INF_F;
    #pragma unroll 4
    for (int j = tid; j < valid; j += 256) {
        vals[cnt] = p[j];
        m = fmaxf(m, vals[cnt]);
        cnt++;
    }
    m = warpRedMax(m);
    if (lane == 0) red[wid] = m;
    __syncthreads();
    if (tid == 0) {
        float mm = red[0];
        #pragma unroll
        for (int k = 1; k < 8; k++) mm = fmaxf(mm, red[k]);
        bcast = mm;
    }
    __syncthreads();
    m = bcast;

    float s = 0.0f;
    for (int c = 0; c < cnt; c++) {
        vals[c] = __expf(vals[c] - m);
        s += vals[c];
    }
    s = warpRedSum(s);
    __syncthreads();                   // red[] reuse
    if (lane == 0) red[wid] = s;
    __syncthreads();
    if (tid == 0) {
        float ss = 0.0f;
        #pragma unroll
        for (int k = 0; k < 8; k++) ss += red[k];
        bcast = 1.0f / ss;
    }
    __syncthreads();
    const float inv = bcast;

    cnt = 0;
    #pragma unroll 4
    for (int j = tid; j < valid; j += 256) p[j] = vals[cnt++] * inv;

    const int tileEnd  = (valid + 127) & ~127;         // multiple of 128
    const int vecStart = (valid + 3) & ~3;             // first 4-aligned index
    for (int j = valid + tid; j < vecStart && j < tileEnd; j += 256) p[j] = 0.0f;
    float4 z4 = make_float4(0.f, 0.f, 0.f, 0.f);
    for (int j4 = (vecStart >> 2) + tid; j4 < (tileEnd >> 2); j4 += 256)
        reinterpret_cast<float4*>(p)[j4] = z4;
}

// ---------------------------------------------------------------------------
// Kernel 4: att_output = att_weights @ V.  Causal truncation of the k-loop
// at the diagonal tile.  grid = (8, 16, BATCH).
// ---------------------------------------------------------------------------
__global__ __launch_bounds__(256, 2) void out_gemm(
    const float* __restrict__ w, float* __restrict__ out)
{
    __shared__ float As[2][BK][128 + PAD];
    __shared__ float Bs[2][BK][128 + PAD];

    const int tid = threadIdx.x;
    const int tx  = tid & 15;
    const int ty  = tid >> 4;
    const int qt  = blockIdx.y;
    const int rowBase = qt * 128;
    const int colBase = blockIdx.x * 128;
    const int b = blockIdx.z;

    const float* A  = w   + (size_t)b * SEQ * SEQ;   // [SEQ, SEQ]
    const float* Bv = g_v + (size_t)b * SEQ * DIM;   // [SEQ, DIM]
    float*       C  = out + (size_t)b * SEQ * DIM;

    const int ar_ = tid >> 1;
    const int ac_ = (tid & 1) * 4;
    const float* aPtr = &A[(size_t)(rowBase + ar_) * SEQ + ac_];
    const int br_ = tid >> 5;
    const int bc_ = (tid & 31) * 4;
    const float* bPtr = &Bv[(size_t)br_ * DIM + colBase + bc_];

    unsigned long long acc2[8][4];
    #pragma unroll
    for (int u = 0; u < 8; u++)
        #pragma unroll
        for (int v = 0; v < 4; v++) acc2[u][v] = 0ULL;

    const int nt = ((qt + 1) * 128) / BK;   // causal truncation

    float4 apf = *reinterpret_cast<const float4*>(aPtr);
    float4 bpf = *reinterpret_cast<const float4*>(bPtr);
    As[0][ac_ + 0][ar_] = apf.x; As[0][ac_ + 1][ar_] = apf.y;
    As[0][ac_ + 2][ar_] = apf.z; As[0][ac_ + 3][ar_] = apf.w;
    *reinterpret_cast<float4*>(&Bs[0][br_][bc_]) = bpf;
    __syncthreads();

    for (int t = 0; t < nt; t++) {
        const int buf = t & 1;
        const bool more = (t + 1 < nt);
        if (more) {
            aPtr += BK;
            bPtr += (size_t)BK * DIM;
            apf = *reinterpret_cast<const float4*>(aPtr);
            bpf = *reinterpret_cast<const float4*>(bPtr);
        }
        mma_tile(As[buf], Bs[buf], tx, ty, acc2);
        if (more) {
            As[1 - buf][ac_ + 0][ar_] = apf.x; As[1 - buf][ac_ + 1][ar_] = apf.y;
            As[1 - buf][ac_ + 2][ar_] = apf.z; As[1 - buf][ac_ + 3][ar_] = apf.w;
            *reinterpret_cast<float4*>(&Bs[1 - buf][br_][bc_]) = bpf;
            __syncthreads();
        }
    }

    #pragma unroll
    for (int u = 0; u < 8; u++) {
        int ru = rowBase + ((u < 4) ? (ty * 4 + u) : (64 + ty * 4 + (u - 4)));
        float c[8];
        unpack_row(acc2[u], c);
        #pragma unroll
        for (int half = 0; half < 2; half++) {
            float4 vv;
            vv.x = c[half * 4 + 0];
            vv.y = c[half * 4 + 1];
            vv.z = c[half * 4 + 2];
            vv.w = c[half * 4 + 3];
            int cc = colBase + half * 64 + tx * 4;
            *reinterpret_cast<float4*>(&C[(size_t)ru * DIM + cc]) = vv;
        }
    }
}

// ---------------------------------------------------------------------------
// kernel_launch: x, Wq, Wk, Wv -> (att_output, att_weights) concatenated.
// ---------------------------------------------------------------------------
extern "C" void kernel_launch(void* const* d_in, const int* in_sizes, int n_in,
                              void* d_out, int out_size)
{
    const float* x  = (const float*)d_in[0];
    const float* Wq = (const float*)d_in[1];
    const float* Wk = (const float*)d_in[2];
    const float* Wv = (const float*)d_in[3];

    float* att_out = (float*)d_out;                               // B*S*D
    float* att_w   = (float*)d_out + (size_t)BATCH * SEQ * DIM;   // B*S*S

    qkv_gemm<<<dim3(DIM / 128, MTOT / 128, 3), 256>>>(x, Wq, Wk, Wv);
    scores_gemm<<<dim3(SEQ / 128, SEQ / 128, BATCH), 256>>>(att_w);
    softmax_rows<<<dim3(BATCH * SEQ), 256>>>(att_w);
    out_gemm<<<dim3(DIM / 128, SEQ / 128, BATCH), 256>>>(att_w, att_out);
}